// round 13
// baseline (speedup 1.0000x reference)
#include <cuda_runtime.h>
#include <cuda_bf16.h>
#include <cuda_fp16.h>
#include <cstdint>

// ---------------------------------------------------------------------------
// Problem constants
#define N_ROWS   32768          // B*H*W*L = 8*16*16*16
#define K_CODES  1024
#define D_DIM    256
#define S_SZ     4096
#define QUANT_ELEMS 8388608     // 8*256*4096

// GEMM tiling: CTA = 128 rows x ALL 1024 codes (8 N-tiles of 128), 8 warps,
// warp tile 32x64. A resident (reused 8x), B double-buffered w/ cross-tile
// prefetch. Select phase fused at CTA tail (scores L2-hot).
#define BM 128
#define BKN 128
#define KC 64                   // bf16 k-chunk (128 bytes/row)

// smem: A (4 sub-tiles, 64KB) | B0|B1 (16KB each) | bnorm (4KB) | pmin (1KB)
#define SM_A       0
#define SM_B       65536
#define SM_BNORM   98304
#define SM_PMIN    102400
#define SM_TOTAL   103424

// ---------------------------------------------------------------------------
// Scratch (__device__ globals; no runtime allocation)
__device__ __nv_bfloat16 g_zbf[N_ROWS * D_DIM];      // z transposed (n,d) bf16
__device__ float  g_zt[N_ROWS * D_DIM];              // z transposed (n,d) fp32
__device__ __nv_bfloat16 g_cbbf[K_CODES * D_DIM];    // codebook bf16
__device__ __half g_scores_h[N_ROWS * K_CODES];      // approx scores fp16 (64 MB)
__device__ float  g_a[N_ROWS];                       // ||z_n||^2 (sequential-d fmaf!)
__device__ float  g_sabs[N_ROWS];                    // sum_d |z_nd|
__device__ float  g_b[K_CODES];                      // ||e_k||^2
__device__ int    g_idx[N_ROWS];                     // final indices
__device__ double g_part[8192];                      // loss partials

// ---------------------------------------------------------------------------
__device__ __forceinline__ uint32_t smem_u32(const void* p) {
    uint32_t a;
    asm("{ .reg .u64 t; cvta.to.shared.u64 t, %1; cvt.u32.u64 %0, t; }" : "=r"(a) : "l"(p));
    return a;
}
#define SW128(o) ((o) ^ (((o) >> 3) & 0x70))

__device__ __forceinline__ void cp16(uint32_t saddr, const void* gaddr) {
    asm volatile("cp.async.cg.shared.global [%0], [%1], 16;" :: "r"(saddr), "l"(gaddr));
}
#define CP_COMMIT() asm volatile("cp.async.commit_group;")
#define CP_WAIT(n)  asm volatile("cp.async.wait_group %0;" :: "n"(n))

__device__ __forceinline__ void ldsm_x4(uint32_t* r, uint32_t saddr) {
    asm volatile("ldmatrix.sync.aligned.m8n8.x4.shared.b16 {%0,%1,%2,%3}, [%4];"
                 : "=r"(r[0]), "=r"(r[1]), "=r"(r[2]), "=r"(r[3]) : "r"(saddr));
}
__device__ __forceinline__ void mma_bf16(float* c, const uint32_t* a, uint32_t b0, uint32_t b1) {
    asm volatile("mma.sync.aligned.m16n8k16.row.col.f32.bf16.bf16.f32 "
                 "{%0,%1,%2,%3}, {%4,%5,%6,%7}, {%8,%9}, {%0,%1,%2,%3};"
                 : "+f"(c[0]), "+f"(c[1]), "+f"(c[2]), "+f"(c[3])
                 : "r"(a[0]), "r"(a[1]), "r"(a[2]), "r"(a[3]), "r"(b0), "r"(b1));
}

__device__ __forceinline__ uint32_t pack_bf16x2(float lo, float hi) {
    __nv_bfloat162 t = __floats2bfloat162_rn(lo, hi);
    uint32_t u;
    memcpy(&u, &t, 4);
    return u;
}

// ---------------------------------------------------------------------------
// 1) Codebook: bf16 convert + ||e_k||^2, warp per row.
__global__ void prep_cbnorm_kernel(const float* __restrict__ cb) {
    int w = blockIdx.x * 8 + (threadIdx.x >> 5);
    int lane = threadIdx.x & 31;
    const float* p = cb + (size_t)w * D_DIM + lane * 8;
    float4 v0 = *(const float4*)p;
    float4 v1 = *(const float4*)(p + 4);
    uint4 packed;
    packed.x = pack_bf16x2(v0.x, v0.y);
    packed.y = pack_bf16x2(v0.z, v0.w);
    packed.z = pack_bf16x2(v1.x, v1.y);
    packed.w = pack_bf16x2(v1.z, v1.w);
    *(uint4*)(g_cbbf + (size_t)w * D_DIM + lane * 8) = packed;
    float acc = 0.0f;
    acc = fmaf(v0.x, v0.x, acc); acc = fmaf(v0.y, v0.y, acc);
    acc = fmaf(v0.z, v0.z, acc); acc = fmaf(v0.w, v0.w, acc);
    acc = fmaf(v1.x, v1.x, acc); acc = fmaf(v1.y, v1.y, acc);
    acc = fmaf(v1.z, v1.z, acc); acc = fmaf(v1.w, v1.w, acc);
    #pragma unroll
    for (int off = 16; off > 0; off >>= 1)
        acc += __shfl_xor_sync(0xffffffffu, acc, off);
    if (lane == 0) g_b[w] = acc;
}

// ---------------------------------------------------------------------------
// 2) Fused: transpose z -> (n,d) fp32 + bf16, AND per-row sequential norms.
__global__ void __launch_bounds__(256)
prep_z_kernel(const float* __restrict__ z) {
    __shared__ float tile[32][257];                 // [s][d], bank(s+d)
    int x = threadIdx.x & 31, y = threadIdx.x >> 5; // lane, warp
    int s0 = blockIdx.x * 32;
    int b  = blockIdx.y;
    const float* zb = z + (size_t)b * (D_DIM * S_SZ) + s0;
    #pragma unroll 8
    for (int i = 0; i < 32; i++) {
        int d = y + 8 * i;
        tile[x][d] = zb[(size_t)d * S_SZ + x];
    }
    __syncthreads();
    #pragma unroll
    for (int rr = 0; rr < 4; rr++) {
        int r = y * 4 + rr;
        size_t n = (size_t)(b * S_SZ + s0 + r);
        #pragma unroll
        for (int c = 0; c < 8; c++) {
            int d = c * 32 + x;
            float v = tile[r][d];
            g_zt[n * D_DIM + d]  = v;
            g_zbf[n * D_DIM + d] = __float2bfloat16(v);
        }
    }
    if (threadIdx.x < 32) {
        int r = threadIdx.x;
        float acc = 0.0f, sab = 0.0f;
        #pragma unroll 8
        for (int d = 0; d < D_DIM; d++) {
            float v = tile[r][d];
            acc = fmaf(v, v, acc);
            sab += fabsf(v);
        }
        int n = b * S_SZ + s0 + r;
        g_a[n] = acc;
        g_sabs[n] = sab;
    }
}

// ---------------------------------------------------------------------------
// 3) Fused HMMA GEMM + argmin-select. CTA = 128 rows x all 1024 codes.
__global__ void __launch_bounds__(256, 2)
mma_select_kernel(const float* __restrict__ cb, float* __restrict__ out_idx) {
    extern __shared__ char smem[];
    uint32_t sb = smem_u32(smem);
    int tid  = threadIdx.x;
    int wid  = tid >> 5, lane = tid & 31;
    int wm   = wid & 3;              // 0..3  (32-row slice)
    int wn   = wid >> 2;             // 0..1  (64-col slice)
    int n0   = blockIdx.x * BM;

    float* bsh  = (float*)(smem + SM_BNORM);   // 1024 code norms
    float* pmin = (float*)(smem + SM_PMIN);    // [128][2] partial row mins
    #pragma unroll
    for (int i = 0; i < 4; i++) bsh[tid + 256 * i] = g_b[tid + 256 * i];

    int lrow = tid >> 1;
    int lseg0 = (tid & 1) * 4;

    auto load_B = [&](int buf, int k0, int c) {
        uint32_t bbase = sb + SM_B + buf * 16384;
        const __nv_bfloat16* bg = g_cbbf + (size_t)(k0 + lrow) * D_DIM + c * KC;
        #pragma unroll
        for (int i = 0; i < 4; i++) {
            int seg = lseg0 + i;
            cp16(bbase + SW128(lrow * 128 + seg * 16), bg + seg * 8);
        }
    };

    // Prologue: all of A (reused for all 8 N-tiles) + first B chunk
    {
        const __nv_bfloat16* ag = g_zbf + (size_t)(n0 + lrow) * D_DIM;
        #pragma unroll
        for (int c = 0; c < 4; c++) {
            uint32_t abase = sb + SM_A + c * 16384;
            #pragma unroll
            for (int i = 0; i < 4; i++) {
                int seg = lseg0 + i;
                cp16(abase + SW128(lrow * 128 + seg * 16), ag + c * KC + seg * 8);
            }
        }
        load_B(0, 0, 0);
        CP_COMMIT();
    }

    int lr = lane & 15;
    int lh = lane >> 4;
    int gq = lane >> 2;
    int qc = (lane & 3) * 2;

    float rmin[2][2] = {{1e30f, 1e30f}, {1e30f, 1e30f}};

    for (int nt = 0; nt < 8; nt++) {
        int k0 = nt * BKN;
        float C[2][8][4];
        #pragma unroll
        for (int mf = 0; mf < 2; mf++)
            #pragma unroll
            for (int nf = 0; nf < 8; nf++)
                #pragma unroll
                for (int q = 0; q < 4; q++) C[mf][nf][q] = 0.0f;

        for (int c = 0; c < 4; c++) {
            if (c < 3)       { load_B((c + 1) & 1, k0, c + 1); CP_COMMIT(); CP_WAIT(1); }
            else if (nt < 7) { load_B(0, k0 + BKN, 0);         CP_COMMIT(); CP_WAIT(1); }
            else             { CP_WAIT(0); }
            __syncthreads();

            uint32_t abase = sb + SM_A + c * 16384;
            uint32_t bbase = sb + SM_B + (c & 1) * 16384;

            #pragma unroll
            for (int ks = 0; ks < 4; ks++) {
                uint32_t a[2][4], bq[4][4];
                #pragma unroll
                for (int mf = 0; mf < 2; mf++) {
                    int r = wm * 32 + mf * 16 + lr;
                    ldsm_x4(a[mf], abase + SW128(r * 128 + (2 * ks + lh) * 16));
                }
                #pragma unroll
                for (int nf2 = 0; nf2 < 4; nf2++) {
                    int r = wn * 64 + nf2 * 16 + lr;
                    ldsm_x4(bq[nf2], bbase + SW128(r * 128 + (2 * ks + lh) * 16));
                }
                #pragma unroll
                for (int mf = 0; mf < 2; mf++)
                    #pragma unroll
                    for (int nf2 = 0; nf2 < 4; nf2++) {
                        mma_bf16(C[mf][2 * nf2],     a[mf], bq[nf2][0], bq[nf2][2]);
                        mma_bf16(C[mf][2 * nf2 + 1], a[mf], bq[nf2][1], bq[nf2][3]);
                    }
            }
            __syncthreads();
        }

        // Epilogue: fp16 score stores + register running row-min
        #pragma unroll
        for (int mf = 0; mf < 2; mf++) {
            int r0 = n0 + wm * 32 + mf * 16 + gq;
            float m0 = 1e30f, m1 = 1e30f;
            #pragma unroll
            for (int nf = 0; nf < 8; nf++) {
                int colL = wn * 64 + nf * 8 + qc;
                int kk = k0 + colL;
                float b0v = bsh[kk], b1v = bsh[kk + 1];
                float s00 = b0v - 2.0f * C[mf][nf][0];
                float s01 = b1v - 2.0f * C[mf][nf][1];
                float s10 = b0v - 2.0f * C[mf][nf][2];
                float s11 = b1v - 2.0f * C[mf][nf][3];
                *(__half2*)(g_scores_h + (size_t)r0 * K_CODES + kk) =
                    __floats2half2_rn(s00, s01);
                *(__half2*)(g_scores_h + (size_t)(r0 + 8) * K_CODES + kk) =
                    __floats2half2_rn(s10, s11);
                m0 = fminf(m0, fminf(s00, s01));
                m1 = fminf(m1, fminf(s10, s11));
            }
            m0 = fminf(m0, __shfl_xor_sync(0xffffffffu, m0, 1));
            m0 = fminf(m0, __shfl_xor_sync(0xffffffffu, m0, 2));
            m1 = fminf(m1, __shfl_xor_sync(0xffffffffu, m1, 1));
            m1 = fminf(m1, __shfl_xor_sync(0xffffffffu, m1, 2));
            rmin[mf][0] = fminf(rmin[mf][0], m0);
            rmin[mf][1] = fminf(rmin[mf][1], m1);
        }
    }

    // Publish row mins
    if ((lane & 3) == 0) {
        #pragma unroll
        for (int mf = 0; mf < 2; mf++) {
            int r0 = wm * 32 + mf * 16 + gq;          // local row
            pmin[r0 * 2 + wn]       = rmin[mf][0];
            pmin[(r0 + 8) * 2 + wn] = rmin[mf][1];
        }
    }
    __syncthreads();

    // Select phase: warp handles rows [wid*16, wid*16+16). Scores L2/L1-hot.
    for (int rr = 0; rr < 16; rr++) {
        int rloc = wid * 16 + rr;
        int n = n0 + rloc;
        float minv = fminf(pmin[rloc * 2], pmin[rloc * 2 + 1]);
        float thresh = minv + g_sabs[n] * 1.6e-5f + 7.0e-4f;
        float a = g_a[n];

        const float* zp = g_zt + (size_t)n * D_DIM + lane * 8;
        float4 z0 = *(const float4*)zp;
        float4 z1 = *(const float4*)(zp + 4);

        const __half* sr = g_scores_h + (size_t)n * K_CODES;
        const uint4* sp = (const uint4*)(sr + lane * 32);
        uint4 u[4];
        u[0] = sp[0]; u[1] = sp[1]; u[2] = sp[2]; u[3] = sp[3];

        unsigned lmask = 0;
        #pragma unroll
        for (int q = 0; q < 4; q++) {
            const __half2* h = (const __half2*)&u[q];
            #pragma unroll
            for (int e = 0; e < 4; e++) {
                float2 v = __half22float2(h[e]);
                if (v.x <= thresh) lmask |= (1u << (q * 8 + e * 2));
                if (v.y <= thresh) lmask |= (1u << (q * 8 + e * 2 + 1));
            }
        }

        unsigned long long best = ~0ULL;
        unsigned has = __ballot_sync(0xffffffffu, lmask != 0);
        while (has) {
            int owner = __ffs(has) - 1;
            has &= has - 1;
            unsigned m = __shfl_sync(0xffffffffu, lmask, owner);
            while (m) {
                int e = __ffs(m) - 1;
                m &= m - 1;
                int kc = owner * 32 + e;
                const float* ep = cb + (size_t)kc * D_DIM + lane * 8;
                float4 e0 = *(const float4*)ep;
                float4 e1 = *(const float4*)(ep + 4);
                float acc = 0.0f;
                acc = fmaf(z0.x, e0.x, acc); acc = fmaf(z0.y, e0.y, acc);
                acc = fmaf(z0.z, e0.z, acc); acc = fmaf(z0.w, e0.w, acc);
                acc = fmaf(z1.x, e1.x, acc); acc = fmaf(z1.y, e1.y, acc);
                acc = fmaf(z1.z, e1.z, acc); acc = fmaf(z1.w, e1.w, acc);
                #pragma unroll
                for (int off = 16; off > 0; off >>= 1)
                    acc += __shfl_xor_sync(0xffffffffu, acc, off);
                float tsum = a + bsh[kc];                // fl(a + b)
                float dv = tsum - 2.0f * acc;            // fl(t - 2c)
                unsigned long long p =
                    ((unsigned long long)__float_as_uint(dv) << 32) | (unsigned)kc;
                best = min(best, p);
            }
        }
        if (lane == 0) {
            int kk = (int)(unsigned)(best & 0xFFFFFFFFULL);
            g_idx[n] = kk;
            out_idx[n] = (float)kk;
        }
    }
}

// ---------------------------------------------------------------------------
// 4) Gather + straight-through + loss partials
__global__ void gather_loss_kernel(const float* __restrict__ z,
                                   const float* __restrict__ cb,
                                   float* __restrict__ out_q) {
    int gid4 = blockIdx.x * blockDim.x + threadIdx.x;
    int base = gid4 * 4;
    int s = base & 4095;
    int r = base >> 12;
    int d = r & 255;
    int b = r >> 8;
    int n = b * S_SZ + s;
    float4 zv = *(const float4*)(z + base);
    float4 ov;
    int k0 = g_idx[n], k1 = g_idx[n + 1], k2 = g_idx[n + 2], k3 = g_idx[n + 3];
    float q0 = cb[(size_t)k0 * D_DIM + d];
    float q1 = cb[(size_t)k1 * D_DIM + d];
    float q2 = cb[(size_t)k2 * D_DIM + d];
    float q3 = cb[(size_t)k3 * D_DIM + d];
    float d0 = q0 - zv.x, d1 = q1 - zv.y, d2 = q2 - zv.z, d3 = q3 - zv.w;
    ov.x = zv.x + d0; ov.y = zv.y + d1; ov.z = zv.z + d2; ov.w = zv.w + d3;
    *(float4*)(out_q + base) = ov;
    float part = fmaf(d0, d0, fmaf(d1, d1, fmaf(d2, d2, d3 * d3)));
    #pragma unroll
    for (int off = 16; off > 0; off >>= 1)
        part += __shfl_down_sync(0xffffffffu, part, off);
    __shared__ float ws[8];
    int lane = threadIdx.x & 31, w = threadIdx.x >> 5;
    if (lane == 0) ws[w] = part;
    __syncthreads();
    if (threadIdx.x == 0) {
        double s8 = 0.0;
        #pragma unroll
        for (int i = 0; i < 8; i++) s8 += (double)ws[i];
        g_part[blockIdx.x] = s8;
    }
}

__global__ void finalize_loss_kernel(float* __restrict__ out_loss) {
    __shared__ double ws[256];
    double acc = 0.0;
    for (int i = threadIdx.x; i < 8192; i += 256) acc += g_part[i];
    ws[threadIdx.x] = acc;
    __syncthreads();
    for (int off = 128; off > 0; off >>= 1) {
        if (threadIdx.x < off) ws[threadIdx.x] += ws[threadIdx.x + off];
        __syncthreads();
    }
    if (threadIdx.x == 0) {
        double mse = ws[0] / (double)QUANT_ELEMS;
        out_loss[0] = (float)(1.25 * mse);
    }
}

// ---------------------------------------------------------------------------
extern "C" void kernel_launch(void* const* d_in, const int* in_sizes, int n_in,
                              void* d_out, int out_size) {
    const float* z  = (const float*)d_in[0];
    const float* cb = (const float*)d_in[1];
    float* out      = (float*)d_out;
    float* out_q    = out;
    float* out_idx  = out + QUANT_ELEMS;
    float* out_loss = out + QUANT_ELEMS + N_ROWS;

    cudaFuncSetAttribute(mma_select_kernel,
                         cudaFuncAttributeMaxDynamicSharedMemorySize, SM_TOTAL);

    prep_cbnorm_kernel<<<K_CODES / 8, 256>>>(cb);
    prep_z_kernel<<<dim3(S_SZ / 32, 8), 256>>>(z);
    mma_select_kernel<<<N_ROWS / BM, 256, SM_TOTAL>>>(cb, out_idx);
    gather_loss_kernel<<<QUANT_ELEMS / 4 / 256, 256>>>(z, cb, out_q);
    finalize_loss_kernel<<<1, 256>>>(out_loss);
}

// round 15
// speedup vs baseline: 1.2586x; 1.2586x over previous
#include <cuda_runtime.h>
#include <cuda_bf16.h>
#include <cuda_fp16.h>
#include <cstdint>

// ---------------------------------------------------------------------------
// Problem constants
#define N_ROWS   32768          // B*H*W*L = 8*16*16*16
#define K_CODES  1024
#define D_DIM    256
#define S_SZ     4096
#define QUANT_ELEMS 8388608     // 8*256*4096

// GEMM tiling (R10 proven config): CTA 128x128, 8 warps, warp tile 32x64
#define BM 128
#define BKN 128
#define KC 64                   // bf16 k-chunk (128 bytes/row)

// smem layout (dynamic): A0 | B0 | A1 | B1 | bnorm
#define TILE_BYTES 16384        // 128 rows x 128B
#define SM_BNORM   65536
#define SM_TOTAL   66048

// gather tiling
#define GD 32                   // d per tile
#define GS 128                  // s per tile

// ---------------------------------------------------------------------------
// Scratch (__device__ globals; no runtime allocation)
__device__ __nv_bfloat16 g_zbf[N_ROWS * D_DIM];      // z transposed (n,d) bf16
__device__ float  g_zt[N_ROWS * D_DIM];              // z transposed (n,d) fp32
__device__ __nv_bfloat16 g_cbbf[K_CODES * D_DIM];    // codebook bf16
__device__ __half g_scores_h[N_ROWS * K_CODES];      // approx scores fp16 (64 MB)
__device__ float  g_a[N_ROWS];                       // ||z_n||^2 (sequential-d fmaf!)
__device__ float  g_sabs[N_ROWS];                    // sum_d |z_nd|
__device__ float  g_b[K_CODES];                      // ||e_k||^2
__device__ int    g_idx[N_ROWS];                     // final indices
__device__ double g_part[2048];                      // loss partials

// ---------------------------------------------------------------------------
__device__ __forceinline__ uint32_t smem_u32(const void* p) {
    uint32_t a;
    asm("{ .reg .u64 t; cvta.to.shared.u64 t, %1; cvt.u32.u64 %0, t; }" : "=r"(a) : "l"(p));
    return a;
}
#define SW128(o) ((o) ^ (((o) >> 3) & 0x70))

__device__ __forceinline__ void cp16(uint32_t saddr, const void* gaddr) {
    asm volatile("cp.async.cg.shared.global [%0], [%1], 16;" :: "r"(saddr), "l"(gaddr));
}
#define CP_COMMIT() asm volatile("cp.async.commit_group;")
#define CP_WAIT(n)  asm volatile("cp.async.wait_group %0;" :: "n"(n))

__device__ __forceinline__ void ldsm_x4(uint32_t* r, uint32_t saddr) {
    asm volatile("ldmatrix.sync.aligned.m8n8.x4.shared.b16 {%0,%1,%2,%3}, [%4];"
                 : "=r"(r[0]), "=r"(r[1]), "=r"(r[2]), "=r"(r[3]) : "r"(saddr));
}
__device__ __forceinline__ void mma_bf16(float* c, const uint32_t* a, uint32_t b0, uint32_t b1) {
    asm volatile("mma.sync.aligned.m16n8k16.row.col.f32.bf16.bf16.f32 "
                 "{%0,%1,%2,%3}, {%4,%5,%6,%7}, {%8,%9}, {%0,%1,%2,%3};"
                 : "+f"(c[0]), "+f"(c[1]), "+f"(c[2]), "+f"(c[3])
                 : "r"(a[0]), "r"(a[1]), "r"(a[2]), "r"(a[3]), "r"(b0), "r"(b1));
}

__device__ __forceinline__ uint32_t pack_bf16x2(float lo, float hi) {
    __nv_bfloat162 t = __floats2bfloat162_rn(lo, hi);
    uint32_t u;
    memcpy(&u, &t, 4);
    return u;
}

// ---------------------------------------------------------------------------
// 1) Codebook: bf16 convert + ||e_k||^2, warp per row.
__global__ void prep_cbnorm_kernel(const float* __restrict__ cb) {
    int w = blockIdx.x * 8 + (threadIdx.x >> 5);
    int lane = threadIdx.x & 31;
    const float* p = cb + (size_t)w * D_DIM + lane * 8;
    float4 v0 = *(const float4*)p;
    float4 v1 = *(const float4*)(p + 4);
    uint4 packed;
    packed.x = pack_bf16x2(v0.x, v0.y);
    packed.y = pack_bf16x2(v0.z, v0.w);
    packed.z = pack_bf16x2(v1.x, v1.y);
    packed.w = pack_bf16x2(v1.z, v1.w);
    *(uint4*)(g_cbbf + (size_t)w * D_DIM + lane * 8) = packed;
    float acc = 0.0f;
    acc = fmaf(v0.x, v0.x, acc); acc = fmaf(v0.y, v0.y, acc);
    acc = fmaf(v0.z, v0.z, acc); acc = fmaf(v0.w, v0.w, acc);
    acc = fmaf(v1.x, v1.x, acc); acc = fmaf(v1.y, v1.y, acc);
    acc = fmaf(v1.z, v1.z, acc); acc = fmaf(v1.w, v1.w, acc);
    #pragma unroll
    for (int off = 16; off > 0; off >>= 1)
        acc += __shfl_xor_sync(0xffffffffu, acc, off);
    if (lane == 0) g_b[w] = acc;
}

// ---------------------------------------------------------------------------
// 2) Fused: transpose z -> (n,d) fp32 + bf16, AND per-row sequential norms.
__global__ void __launch_bounds__(256)
prep_z_kernel(const float* __restrict__ z) {
    __shared__ float tile[32][257];                 // [s][d], bank(s+d)
    int x = threadIdx.x & 31, y = threadIdx.x >> 5; // lane, warp
    int s0 = blockIdx.x * 32;
    int b  = blockIdx.y;
    const float* zb = z + (size_t)b * (D_DIM * S_SZ) + s0;
    #pragma unroll 8
    for (int i = 0; i < 32; i++) {
        int d = y + 8 * i;
        tile[x][d] = zb[(size_t)d * S_SZ + x];
    }
    __syncthreads();
    #pragma unroll
    for (int rr = 0; rr < 4; rr++) {
        int r = y * 4 + rr;
        size_t n = (size_t)(b * S_SZ + s0 + r);
        #pragma unroll
        for (int c = 0; c < 8; c++) {
            int d = c * 32 + x;
            float v = tile[r][d];
            g_zt[n * D_DIM + d]  = v;
            g_zbf[n * D_DIM + d] = __float2bfloat16(v);
        }
    }
    if (threadIdx.x < 32) {
        int r = threadIdx.x;
        float acc = 0.0f, sab = 0.0f;
        #pragma unroll 8
        for (int d = 0; d < D_DIM; d++) {
            float v = tile[r][d];
            acc = fmaf(v, v, acc);
            sab += fabsf(v);
        }
        int n = b * S_SZ + s0 + r;
        g_a[n] = acc;
        g_sabs[n] = sab;
    }
}

// ---------------------------------------------------------------------------
// 3) HMMA bf16 GEMM (R10 form): fp16 score stores only.
__global__ void __launch_bounds__(256, 2)
mma_kernel() {
    extern __shared__ char smem[];
    uint32_t sb = smem_u32(smem);
    int tid  = threadIdx.x;
    int wid  = tid >> 5, lane = tid & 31;
    int wm   = wid & 3;              // 0..3  (32-row slice)
    int wn   = wid >> 2;             // 0..1  (64-col slice)
    int n0   = blockIdx.x * BM;
    int k0   = blockIdx.y * BKN;

    float* bsh = (float*)(smem + SM_BNORM);
    if (tid < BKN) bsh[tid] = g_b[k0 + tid];

    int lrow = tid >> 1;
    int lseg0 = (tid & 1) * 4;
    auto load_chunk = [&](int buf, int c) {
        uint32_t abase = sb + buf * 32768;
        uint32_t bbase = abase + TILE_BYTES;
        const __nv_bfloat16* ag = g_zbf  + (size_t)(n0 + lrow) * D_DIM + c * KC;
        const __nv_bfloat16* bg = g_cbbf + (size_t)(k0 + lrow) * D_DIM + c * KC;
        #pragma unroll
        for (int i = 0; i < 4; i++) {
            int seg = lseg0 + i;
            uint32_t soff = SW128(lrow * 128 + seg * 16);
            cp16(abase + soff, ag + seg * 8);
            cp16(bbase + soff, bg + seg * 8);
        }
    };

    float C[2][8][4];
    #pragma unroll
    for (int mf = 0; mf < 2; mf++)
        #pragma unroll
        for (int nf = 0; nf < 8; nf++)
            #pragma unroll
            for (int q = 0; q < 4; q++) C[mf][nf][q] = 0.0f;

    load_chunk(0, 0);
    CP_COMMIT();

    int lr = lane & 15;
    int lh = lane >> 4;

    for (int c = 0; c < 4; c++) {
        if (c < 3) { load_chunk((c + 1) & 1, c + 1); CP_COMMIT(); }
        if (c < 3) { CP_WAIT(1); } else { CP_WAIT(0); }
        __syncthreads();

        uint32_t abase = sb + (c & 1) * 32768;
        uint32_t bbase = abase + TILE_BYTES;

        #pragma unroll
        for (int ks = 0; ks < 4; ks++) {
            uint32_t a[2][4], bq[4][4];
            #pragma unroll
            for (int mf = 0; mf < 2; mf++) {
                int r = wm * 32 + mf * 16 + lr;
                ldsm_x4(a[mf], abase + SW128(r * 128 + (2 * ks + lh) * 16));
            }
            #pragma unroll
            for (int nf2 = 0; nf2 < 4; nf2++) {
                int r = wn * 64 + nf2 * 16 + lr;
                ldsm_x4(bq[nf2], bbase + SW128(r * 128 + (2 * ks + lh) * 16));
            }
            #pragma unroll
            for (int mf = 0; mf < 2; mf++)
                #pragma unroll
                for (int nf2 = 0; nf2 < 4; nf2++) {
                    mma_bf16(C[mf][2 * nf2],     a[mf], bq[nf2][0], bq[nf2][2]);
                    mma_bf16(C[mf][2 * nf2 + 1], a[mf], bq[nf2][1], bq[nf2][3]);
                }
        }
        __syncthreads();
    }

    // Epilogue: fp16 score stores only
    int gq = lane >> 2;
    int qc = (lane & 3) * 2;
    #pragma unroll
    for (int mf = 0; mf < 2; mf++) {
        int r0 = n0 + wm * 32 + mf * 16 + gq;
        #pragma unroll
        for (int nf = 0; nf < 8; nf++) {
            int colL = wn * 64 + nf * 8 + qc;
            int kk = k0 + colL;
            float b0v = bsh[colL], b1v = bsh[colL + 1];
            float s00 = b0v - 2.0f * C[mf][nf][0];
            float s01 = b1v - 2.0f * C[mf][nf][1];
            float s10 = b0v - 2.0f * C[mf][nf][2];
            float s11 = b1v - 2.0f * C[mf][nf][3];
            *(__half2*)(g_scores_h + (size_t)r0 * K_CODES + kk) =
                __floats2half2_rn(s00, s01);
            *(__half2*)(g_scores_h + (size_t)(r0 + 8) * K_CODES + kk) =
                __floats2half2_rn(s10, s11);
        }
    }
}

// ---------------------------------------------------------------------------
// 4) Select: single register-resident scan + exact fp32 rescore. (R10 form)
__global__ void __launch_bounds__(256)
select_kernel(const float* __restrict__ cb, float* __restrict__ out_idx) {
    int w = threadIdx.x >> 5, lane = threadIdx.x & 31;
    int n = blockIdx.x * 8 + w;

    const float* zp = g_zt + (size_t)n * D_DIM + lane * 8;
    float4 z0 = *(const float4*)zp;
    float4 z1 = *(const float4*)(zp + 4);
    float a = g_a[n];

    const __half* sr = g_scores_h + (size_t)n * K_CODES;
    const uint4* sp = (const uint4*)(sr + lane * 32);
    uint4 u[4];
    u[0] = sp[0]; u[1] = sp[1]; u[2] = sp[2]; u[3] = sp[3];

    float f[32];
    #pragma unroll
    for (int q = 0; q < 4; q++) {
        const __half2* h = (const __half2*)&u[q];
        #pragma unroll
        for (int e = 0; e < 4; e++) {
            float2 v = __half22float2(h[e]);
            f[q * 8 + e * 2]     = v.x;
            f[q * 8 + e * 2 + 1] = v.y;
        }
    }

    float minv = f[0];
    #pragma unroll
    for (int e = 1; e < 32; e++) minv = fminf(minv, f[e]);
    #pragma unroll
    for (int off = 16; off > 0; off >>= 1)
        minv = fminf(minv, __shfl_xor_sync(0xffffffffu, minv, off));
    float thresh = minv + g_sabs[n] * 1.6e-5f + 7.0e-4f;

    unsigned lmask = 0;
    #pragma unroll
    for (int e = 0; e < 32; e++)
        if (f[e] <= thresh) lmask |= (1u << e);

    unsigned long long best = ~0ULL;
    unsigned has = __ballot_sync(0xffffffffu, lmask != 0);
    while (has) {
        int owner = __ffs(has) - 1;
        has &= has - 1;
        unsigned m = __shfl_sync(0xffffffffu, lmask, owner);
        while (m) {
            int e = __ffs(m) - 1;
            m &= m - 1;
            int kc = owner * 32 + e;
            const float* ep = cb + (size_t)kc * D_DIM + lane * 8;
            float4 e0 = *(const float4*)ep;
            float4 e1 = *(const float4*)(ep + 4);
            float acc = 0.0f;
            acc = fmaf(z0.x, e0.x, acc); acc = fmaf(z0.y, e0.y, acc);
            acc = fmaf(z0.z, e0.z, acc); acc = fmaf(z0.w, e0.w, acc);
            acc = fmaf(z1.x, e1.x, acc); acc = fmaf(z1.y, e1.y, acc);
            acc = fmaf(z1.z, e1.z, acc); acc = fmaf(z1.w, e1.w, acc);
            #pragma unroll
            for (int off = 16; off > 0; off >>= 1)
                acc += __shfl_xor_sync(0xffffffffu, acc, off);
            float tsum = a + g_b[kc];                // fl(a + b)
            float dv = tsum - 2.0f * acc;            // fl(t - 2c)
            unsigned long long p =
                ((unsigned long long)__float_as_uint(dv) << 32) | (unsigned)kc;
            best = min(best, p);
        }
    }
    if (lane == 0) {
        int kk = (int)(unsigned)(best & 0xFFFFFFFFULL);
        g_idx[n] = kk;
        out_idx[n] = (float)kk;
    }
}

// ---------------------------------------------------------------------------
// 5) Tiled gather: block = (b, 32 d, 128 s). Coalesced cb row-segment reads
//    into smem transpose tile, then coalesced z/out over s. No scattered LDG.
__global__ void __launch_bounds__(256)
gather_loss_kernel(const float* __restrict__ z,
                   const float* __restrict__ cb,
                   float* __restrict__ out_q) {
    __shared__ float qt[GS][GD + 1];   // [s][d], bank (s+d): conflict-free
    __shared__ int   ks[GS];
    __shared__ float ws[8];
    int tid = threadIdx.x;
    int w = tid >> 5, lane = tid & 31;
    int st = blockIdx.x;               // s-tile 0..31
    int dt = blockIdx.y;               // d-tile 0..7
    int b  = blockIdx.z;               // 0..7
    int s0 = st * GS, d0 = dt * GD;

    if (tid < GS) ks[tid] = g_idx[b * S_SZ + s0 + tid];
    __syncthreads();

    // Gather phase: warp w handles s-indices w*16..w*16+15.
    // Each iteration: coalesced 128B read of cb[k][d0..d0+31].
    #pragma unroll
    for (int i = 0; i < 16; i++) {
        int si = w * 16 + i;
        int k = ks[si];
        qt[si][lane] = cb[(size_t)k * D_DIM + d0 + lane];
    }
    __syncthreads();

    // Compute phase: elem = i*256 + tid; d = elem>>7 (0..31), s = elem&127.
    // Warp = 32 consecutive s at fixed d -> z read / out write coalesced 128B.
    float part = 0.0f;
    #pragma unroll
    for (int i = 0; i < 16; i++) {
        int elem = i * 256 + tid;
        int d = elem >> 7, s = elem & 127;
        size_t gidx = (size_t)b * (D_DIM * S_SZ) + (size_t)(d0 + d) * S_SZ + s0 + s;
        float zv = z[gidx];
        float q  = qt[s][d];
        float diff = q - zv;               // fl(q - z)
        out_q[gidx] = zv + diff;           // straight-through: z + fl(q - z)
        part = fmaf(diff, diff, part);
    }

    #pragma unroll
    for (int off = 16; off > 0; off >>= 1)
        part += __shfl_down_sync(0xffffffffu, part, off);
    if (lane == 0) ws[w] = part;
    __syncthreads();
    if (tid == 0) {
        double s8 = 0.0;
        #pragma unroll
        for (int i = 0; i < 8; i++) s8 += (double)ws[i];
        int bid = blockIdx.x + 32 * (blockIdx.y + 8 * blockIdx.z);
        g_part[bid] = s8;
    }
}

__global__ void finalize_loss_kernel(float* __restrict__ out_loss) {
    __shared__ double ws[256];
    double acc = 0.0;
    for (int i = threadIdx.x; i < 2048; i += 256) acc += g_part[i];
    ws[threadIdx.x] = acc;
    __syncthreads();
    for (int off = 128; off > 0; off >>= 1) {
        if (threadIdx.x < off) ws[threadIdx.x] += ws[threadIdx.x + off];
        __syncthreads();
    }
    if (threadIdx.x == 0) {
        double mse = ws[0] / (double)QUANT_ELEMS;
        out_loss[0] = (float)(1.25 * mse);
    }
}

// ---------------------------------------------------------------------------
extern "C" void kernel_launch(void* const* d_in, const int* in_sizes, int n_in,
                              void* d_out, int out_size) {
    const float* z  = (const float*)d_in[0];
    const float* cb = (const float*)d_in[1];
    float* out      = (float*)d_out;
    float* out_q    = out;
    float* out_idx  = out + QUANT_ELEMS;
    float* out_loss = out + QUANT_ELEMS + N_ROWS;

    cudaFuncSetAttribute(mma_kernel, cudaFuncAttributeMaxDynamicSharedMemorySize, SM_TOTAL);

    prep_cbnorm_kernel<<<K_CODES / 8, 256>>>(cb);
    prep_z_kernel<<<dim3(S_SZ / 32, 8), 256>>>(z);
    mma_kernel<<<dim3(N_ROWS / BM, K_CODES / BKN), 256, SM_TOTAL>>>();
    select_kernel<<<N_ROWS / 8, 256>>>(cb, out_idx);
    gather_loss_kernel<<<dim3(S_SZ / GS, D_DIM / GD, 8), 256>>>(z, cb, out_q);
    finalize_loss_kernel<<<1, 256>>>(out_loss);
}